// round 1
// baseline (speedup 1.0000x reference)
#include <cuda_runtime.h>
#include <cstdint>

// Problem constants (fixed by setup_inputs)
#define B_  4
#define T_  12
#define N_  307
#define DE_ 1024
#define H_  16
#define LK_ 153
#define K1_ 154          // LK_+1
#define TK_ 1848         // T_*K1_
#define BT_ 48           // B_*T_
#define SORT_SZ 512

// Scratch: ids_keep_ = [0, ids_keep+1] per (b,t), laid out [b][t][K1] == [b][TK_]
__device__ int g_idsk[B_ * TK_];

// ---------------------------------------------------------------------------
// Kernel 1: bitonic argsort of noise per (b,t); emits mask output and g_idsk.
// ---------------------------------------------------------------------------
__global__ void sort_kernel(const float* __restrict__ noise,
                            float* __restrict__ mask_out) {
    __shared__ unsigned long long s[SORT_SZ];
    const int tid = threadIdx.x;
    const int bt  = blockIdx.x;

    // Pack (orderable float key << 32) | index. Padding = +inf key.
    float v = (tid < N_) ? noise[bt * N_ + tid] : __int_as_float(0x7F800000);
    unsigned u = __float_as_uint(v);
    u = (u & 0x80000000u) ? ~u : (u | 0x80000000u);
    s[tid] = ((unsigned long long)u << 32) | (unsigned)tid;
    __syncthreads();

    // Bitonic sort, ascending
    for (int k = 2; k <= SORT_SZ; k <<= 1) {
        for (int j = k >> 1; j > 0; j >>= 1) {
            int ixj = tid ^ j;
            if (ixj > tid) {
                unsigned long long a = s[tid], b = s[ixj];
                bool up = ((tid & k) == 0);
                if ((a > b) == up) { s[tid] = b; s[ixj] = a; }
            }
            __syncthreads();
        }
    }

    if (tid < N_) {
        int idx = (int)(s[tid] & 0xFFFFFFFFull);
        // mask[b,t,ids_shuffle[k]] = (k >= len_keep)
        mask_out[bt * N_ + idx] = (tid >= LK_) ? 1.0f : 0.0f;
        if (tid < LK_) g_idsk[bt * K1_ + 1 + tid] = idx + 1;
    }
    if (tid == 0) g_idsk[bt * K1_] = 0;
}

// ---------------------------------------------------------------------------
// Kernel 2: x_masked[b,t,k,:] = x[b,t,ids_keep[b,t,k],:]  (float4 row copy)
// ---------------------------------------------------------------------------
__global__ void xgather_kernel(const float4* __restrict__ x,
                               float4* __restrict__ xm) {
    const int i  = blockIdx.x;            // 0 .. BT_*LK_-1
    const int bt = i / LK_;
    const int k  = i - bt * LK_;
    const int id = g_idsk[bt * K1_ + 1 + k] - 1;
    const float4* src = x  + ((size_t)bt * N_ + id) * (DE_ / 4);
    float4*       dst = xm + (size_t)i * (DE_ / 4);
    dst[threadIdx.x] = src[threadIdx.x];   // 256 threads x float4 = 1024 floats
}

// ---------------------------------------------------------------------------
// Kernel 3: bias_sh[b,h,row,j] = attn_bias[b,h,rmap[row],rmap[j]]
//                                + w[h]*(rmap[row]==0 || rmap[j]==0)
// One block per output row (B*H*TK_ = 118272 blocks), coalesced 1848-f writes.
// ---------------------------------------------------------------------------
__global__ void bias_kernel(const float* __restrict__ bias,
                            const float* __restrict__ w,
                            float* __restrict__ out) {
    const int lin = blockIdx.x;           // (b*H + h)*TK_ + row
    const int row = lin % TK_;
    const int bh  = lin / TK_;
    const int h   = bh & (H_ - 1);
    const int b   = bh >> 4;

    const int* __restrict__ rmap = g_idsk + b * TK_;
    const int r_src = rmap[row];
    const float wh  = w[h];
    const float radd = (r_src == 0) ? wh : 0.0f;

    const float* __restrict__ srow =
        bias + ((size_t)bh * (N_ + 1) + r_src) * (N_ + 1);
    float* __restrict__ orow = out + (size_t)lin * TK_;

    for (int j = threadIdx.x; j < TK_; j += blockDim.x) {
        const int c = rmap[j];
        float v = __ldg(srow + c) + radd;
        if (r_src != 0 && c == 0) v += wh;
        orow[j] = v;
    }
}

// ---------------------------------------------------------------------------
extern "C" void kernel_launch(void* const* d_in, const int* in_sizes, int n_in,
                              void* d_out, int out_size) {
    const float* x     = (const float*)d_in[0];  // (4,12,307,1024)
    const float* bias  = (const float*)d_in[1];  // (4,16,308,308)
    const float* w     = (const float*)d_in[2];  // (1,16)
    const float* noise = (const float*)d_in[3];  // (4,12,307)
    // d_in[4] = len_keep (153), compile-time constant here.

    float* out = (float*)d_out;
    const size_t xm_elems   = (size_t)BT_ * LK_ * DE_;   // 7,520,256
    const size_t mask_elems = (size_t)BT_ * N_;          // 14,736
    float* out_xm   = out;
    float* out_mask = out + xm_elems;
    float* out_bias = out + xm_elems + mask_elems;

    sort_kernel<<<BT_, SORT_SZ>>>(noise, out_mask);
    xgather_kernel<<<BT_ * LK_, 256>>>((const float4*)x, (float4*)out_xm);
    bias_kernel<<<B_ * H_ * TK_, 256>>>(bias, w, out_bias);
}

// round 2
// speedup vs baseline: 1.4331x; 1.4331x over previous
#include <cuda_runtime.h>
#include <cstdint>

// Problem constants (fixed by setup_inputs)
#define B_  4
#define T_  12
#define N_  307
#define NP1 308
#define DE_ 1024
#define H_  16
#define LK_ 153
#define K1_ 154          // LK_+1
#define TK_ 1848         // T_*K1_
#define BT_ 48           // B_*T_
#define SORT_SZ 512
#define ROWS_ 8          // output rows per bias block (1848 % 8 == 0)
#define TILES_ (TK_ / ROWS_)   // 231

// Scratch: ids_keep_ = [0, ids_keep+1] per (b,t), laid out [b][t][K1] == [b][TK_]
__device__ int g_idsk[B_ * TK_];

// ---------------------------------------------------------------------------
// Kernel 1: bitonic argsort of noise per (b,t); emits mask output and g_idsk.
// ---------------------------------------------------------------------------
__global__ void sort_kernel(const float* __restrict__ noise,
                            float* __restrict__ mask_out) {
    __shared__ unsigned long long s[SORT_SZ];
    const int tid = threadIdx.x;
    const int bt  = blockIdx.x;

    float v = (tid < N_) ? noise[bt * N_ + tid] : __int_as_float(0x7F800000);
    unsigned u = __float_as_uint(v);
    u = (u & 0x80000000u) ? ~u : (u | 0x80000000u);
    s[tid] = ((unsigned long long)u << 32) | (unsigned)tid;
    __syncthreads();

    for (int k = 2; k <= SORT_SZ; k <<= 1) {
        for (int j = k >> 1; j > 0; j >>= 1) {
            int ixj = tid ^ j;
            if (ixj > tid) {
                unsigned long long a = s[tid], b = s[ixj];
                bool up = ((tid & k) == 0);
                if ((a > b) == up) { s[tid] = b; s[ixj] = a; }
            }
            __syncthreads();
        }
    }

    if (tid < N_) {
        int idx = (int)(s[tid] & 0xFFFFFFFFull);
        mask_out[bt * N_ + idx] = (tid >= LK_) ? 1.0f : 0.0f;
        if (tid < LK_) g_idsk[bt * K1_ + 1 + tid] = idx + 1;
    }
    if (tid == 0) g_idsk[bt * K1_] = 0;
}

// ---------------------------------------------------------------------------
// Kernel 2: x_masked row gather — streaming float4 copy (no cache pollution)
// ---------------------------------------------------------------------------
__global__ void xgather_kernel(const float4* __restrict__ x,
                               float4* __restrict__ xm) {
    const int i  = blockIdx.x;            // 0 .. BT_*LK_-1
    const int bt = i / LK_;
    const int k  = i - bt * LK_;
    const int id = g_idsk[bt * K1_ + 1 + k] - 1;
    const float4* src = x  + ((size_t)bt * N_ + id) * (DE_ / 4);
    float4*       dst = xm + (size_t)i * (DE_ / 4);
    float4 v = __ldcs(src + threadIdx.x);
    __stcs(dst + threadIdx.x, v);
}

// ---------------------------------------------------------------------------
// Kernel 3: bias shuffle. One block = ROWS_ output rows of one (b,h) plane.
// Source rows + column map staged in SMEM; gathers hit smem (~3-4 cyc/warp)
// instead of replay-heavy L1. Output stores are streaming float4.
// ---------------------------------------------------------------------------
__global__ __launch_bounds__(256)
void bias_kernel(const float* __restrict__ bias,
                 const float* __restrict__ w,
                 float* __restrict__ out) {
    __shared__ int   s_map[TK_];               // 7392 B, per-b column/row map
    __shared__ float s_rows[ROWS_][NP1];       // 8 x 308 floats = 9856 B

    const int tile = blockIdx.x % TILES_;
    const int bh   = blockIdx.x / TILES_;
    const int h    = bh & (H_ - 1);
    const int b    = bh >> 4;
    const int row0 = tile * ROWS_;

    const int*   __restrict__ rmap = g_idsk + b * TK_;
    const float* __restrict__ base = bias + (size_t)bh * NP1 * NP1;

    // Stage the column map
    for (int j = threadIdx.x; j < TK_; j += 256) s_map[j] = rmap[j];

    // Stage the ROWS_ gathered source rows (coalesced within each row)
    for (int idx = threadIdx.x; idx < ROWS_ * NP1; idx += 256) {
        const int i = idx / NP1;
        const int c = idx - i * NP1;
        const int r = __ldg(rmap + row0 + i);
        s_rows[i][c] = base[(size_t)r * NP1 + c];
    }
    __syncthreads();

    const float wh = w[h];
    int rs[ROWS_];
    #pragma unroll
    for (int i = 0; i < ROWS_; i++) rs[i] = s_map[row0 + i];

    float* __restrict__ orow = out + ((size_t)bh * TK_ + row0) * TK_;

    // 462 float4 columns per row, 256 threads -> 2 iterations
    for (int j4 = threadIdx.x; j4 < TK_ / 4; j4 += 256) {
        const int4 c4 = ((const int4*)s_map)[j4];
        #pragma unroll
        for (int i = 0; i < ROWS_; i++) {
            const bool r0 = (rs[i] == 0);
            float4 v;
            v.x = s_rows[i][c4.x] + ((r0 | (c4.x == 0)) ? wh : 0.0f);
            v.y = s_rows[i][c4.y] + ((r0 | (c4.y == 0)) ? wh : 0.0f);
            v.z = s_rows[i][c4.z] + ((r0 | (c4.z == 0)) ? wh : 0.0f);
            v.w = s_rows[i][c4.w] + ((r0 | (c4.w == 0)) ? wh : 0.0f);
            __stcs((float4*)(orow + (size_t)i * TK_) + j4, v);
        }
    }
}

// ---------------------------------------------------------------------------
extern "C" void kernel_launch(void* const* d_in, const int* in_sizes, int n_in,
                              void* d_out, int out_size) {
    const float* x     = (const float*)d_in[0];  // (4,12,307,1024)
    const float* bias  = (const float*)d_in[1];  // (4,16,308,308)
    const float* w     = (const float*)d_in[2];  // (1,16)
    const float* noise = (const float*)d_in[3];  // (4,12,307)

    float* out = (float*)d_out;
    const size_t xm_elems   = (size_t)BT_ * LK_ * DE_;   // 7,520,256
    const size_t mask_elems = (size_t)BT_ * N_;          // 14,736
    float* out_xm   = out;
    float* out_mask = out + xm_elems;
    float* out_bias = out + xm_elems + mask_elems;

    sort_kernel<<<BT_, SORT_SZ>>>(noise, out_mask);
    xgather_kernel<<<BT_ * LK_, 256>>>((const float4*)x, (float4*)out_xm);
    bias_kernel<<<B_ * H_ * TILES_, 256>>>(bias, w, out_bias);
}

// round 3
// speedup vs baseline: 1.5019x; 1.0480x over previous
#include <cuda_runtime.h>
#include <cstdint>

// Problem constants (fixed by setup_inputs)
#define B_  4
#define T_  12
#define N_  307
#define NP1 308
#define DE_ 1024
#define H_  16
#define LK_ 153
#define K1_ 154          // LK_+1
#define TK_ 1848         // T_*K1_
#define BT_ 48           // B_*T_
#define SORT_SZ 512
#define ROWS_ 12                 // output rows per bias tile (1848 = 12*154)
#define TILES_ (TK_ / ROWS_)     // 154
#define NBIAS_BLOCKS (B_ * H_ * TILES_)   // 9856
#define NXG_BLOCKS   (BT_ * LK_)          // 7344

// Scratch: ids_keep_ = [0, ids_keep+1] per (b,t), laid out [b][t][K1] == [b][TK_]
__device__ int g_idsk[B_ * TK_];

// ---------------------------------------------------------------------------
// Kernel 1: bitonic argsort of noise per (b,t); emits mask output and g_idsk.
// ---------------------------------------------------------------------------
__global__ void sort_kernel(const float* __restrict__ noise,
                            float* __restrict__ mask_out) {
    __shared__ unsigned long long s[SORT_SZ];
    const int tid = threadIdx.x;
    const int bt  = blockIdx.x;

    float v = (tid < N_) ? noise[bt * N_ + tid] : __int_as_float(0x7F800000);
    unsigned u = __float_as_uint(v);
    u = (u & 0x80000000u) ? ~u : (u | 0x80000000u);
    s[tid] = ((unsigned long long)u << 32) | (unsigned)tid;
    __syncthreads();

    for (int k = 2; k <= SORT_SZ; k <<= 1) {
        for (int j = k >> 1; j > 0; j >>= 1) {
            int ixj = tid ^ j;
            if (ixj > tid) {
                unsigned long long a = s[tid], b = s[ixj];
                bool up = ((tid & k) == 0);
                if ((a > b) == up) { s[tid] = b; s[ixj] = a; }
            }
            __syncthreads();
        }
    }

    if (tid < N_) {
        int idx = (int)(s[tid] & 0xFFFFFFFFull);
        mask_out[bt * N_ + idx] = (tid >= LK_) ? 1.0f : 0.0f;
        if (tid < LK_) g_idsk[bt * K1_ + 1 + tid] = idx + 1;
    }
    if (tid == 0) g_idsk[bt * K1_] = 0;
}

// ---------------------------------------------------------------------------
// Kernel 2 (fat): bias tiles first, then x_masked row-copy blocks in the tail.
// Bias tile: ROWS_ output rows of one (b,h) plane. Source rows + column map
// staged in SMEM; gathers hit smem instead of replay-heavy L1. Streaming
// float4 stores.
// ---------------------------------------------------------------------------
__global__ __launch_bounds__(256)
void fat_kernel(const float* __restrict__ bias,
                const float* __restrict__ w,
                float* __restrict__ out_bias,
                const float4* __restrict__ x,
                float4* __restrict__ xm) {
    if (blockIdx.x >= NBIAS_BLOCKS) {
        // ---- x_masked gather: one 1024-float row per block ----
        const int i  = blockIdx.x - NBIAS_BLOCKS;   // 0 .. NXG_BLOCKS-1
        const int bt = i / LK_;
        const int k  = i - bt * LK_;
        const int id = __ldg(g_idsk + bt * K1_ + 1 + k) - 1;
        const float4* src = x  + ((size_t)bt * N_ + id) * (DE_ / 4);
        float4*       dst = xm + (size_t)i * (DE_ / 4);
        __stcs(dst + threadIdx.x, __ldcs(src + threadIdx.x));
        return;
    }

    __shared__ int   s_map[TK_];               // 7392 B, per-b column/row map
    __shared__ float s_rows[ROWS_][NP1];       // 12 x 308 floats = 14784 B

    const int tile = blockIdx.x % TILES_;
    const int bh   = blockIdx.x / TILES_;
    const int h    = bh & (H_ - 1);
    const int b    = bh >> 4;
    const int row0 = tile * ROWS_;

    const int*   __restrict__ rmap = g_idsk + b * TK_;
    const float* __restrict__ base = bias + (size_t)bh * NP1 * NP1;

    // Stage the column map
    for (int j = threadIdx.x; j < TK_; j += 256) s_map[j] = rmap[j];

    // Stage the ROWS_ gathered source rows (coalesced within each row)
    for (int idx = threadIdx.x; idx < ROWS_ * NP1; idx += 256) {
        const int i = idx / NP1;
        const int c = idx - i * NP1;
        const int r = __ldg(rmap + row0 + i);
        s_rows[i][c] = base[(size_t)r * NP1 + c];
    }
    __syncthreads();

    const float wh = w[h];
    int rs[ROWS_];
    #pragma unroll
    for (int i = 0; i < ROWS_; i++) rs[i] = s_map[row0 + i];

    float* __restrict__ orow = out_bias + ((size_t)bh * TK_ + row0) * TK_;

    // 462 float4 columns per row, 256 threads -> <=2 iterations
    for (int j4 = threadIdx.x; j4 < TK_ / 4; j4 += 256) {
        const int4 c4 = ((const int4*)s_map)[j4];
        #pragma unroll
        for (int i = 0; i < ROWS_; i++) {
            const bool r0 = (rs[i] == 0);
            float4 v;
            v.x = s_rows[i][c4.x] + ((r0 | (c4.x == 0)) ? wh : 0.0f);
            v.y = s_rows[i][c4.y] + ((r0 | (c4.y == 0)) ? wh : 0.0f);
            v.z = s_rows[i][c4.z] + ((r0 | (c4.z == 0)) ? wh : 0.0f);
            v.w = s_rows[i][c4.w] + ((r0 | (c4.w == 0)) ? wh : 0.0f);
            __stcs((float4*)(orow + (size_t)i * TK_) + j4, v);
        }
    }
}

// ---------------------------------------------------------------------------
extern "C" void kernel_launch(void* const* d_in, const int* in_sizes, int n_in,
                              void* d_out, int out_size) {
    const float* x     = (const float*)d_in[0];  // (4,12,307,1024)
    const float* bias  = (const float*)d_in[1];  // (4,16,308,308)
    const float* w     = (const float*)d_in[2];  // (1,16)
    const float* noise = (const float*)d_in[3];  // (4,12,307)

    float* out = (float*)d_out;
    const size_t xm_elems   = (size_t)BT_ * LK_ * DE_;   // 7,520,256
    const size_t mask_elems = (size_t)BT_ * N_;          // 14,736
    float* out_xm   = out;
    float* out_mask = out + xm_elems;
    float* out_bias = out + xm_elems + mask_elems;

    sort_kernel<<<BT_, SORT_SZ>>>(noise, out_mask);
    fat_kernel<<<NBIAS_BLOCKS + NXG_BLOCKS, 256>>>(
        bias, w, out_bias, (const float4*)x, (float4*)out_xm);
}